// round 17
// baseline (speedup 1.0000x reference)
#include <cuda_runtime.h>
#include <math.h>

#define Nn 10000
#define Ee 160000
#define Ff 4
#define Hh 32
#define Cc 4
#define SORT_NB 148
#define SORT_NT 256
#define SORT_CH 68          // ceil(10000/148)

// ---------------- scratch (device globals; no allocation allowed) -----------
__device__ float g_Qn[Nn * Hh * Hh];       // per-node Q matrices [N, H, H] (40MB)
__device__ float g_r [Nn * Hh];            // per-node b2 contribution r[n,o]
__device__ float g_xA[Nn * Hh];            // ping-pong node features (pre-relu)
__device__ float g_xB[Nn * Hh];
__device__ int    g_cnt[Nn];               // counting sort: histogram
__device__ int    g_cur[Nn];               // counting sort: scatter cursors
__device__ int    g_off[Nn + 1];           // CSR offsets by src
__device__ int    g_sdst[Ee];              // dst sorted by src
__device__ float2 g_sea [Ee];              // edge_attr sorted by src
__device__ int    g_bsum[SORT_NB];         // per-block count sums
__device__ int    g_boff[SORT_NB];         // per-block offsets
__device__ int          g_barArrive = 0;   // grid barrier state
__device__ volatile int g_barGen    = 0;

// ---------------------------------------------------------------------------
// software grid barrier: valid because grid (148 blocks) <= #SMs and the
// stream serializes kernels, so all CTAs are co-resident.
// ---------------------------------------------------------------------------
__device__ __forceinline__ void grid_barrier() {
    __syncthreads();
    if (threadIdx.x == 0) {
        __threadfence();
        int gen = g_barGen;
        if (atomicAdd(&g_barArrive, 1) == SORT_NB - 1) {
            g_barArrive = 0;
            __threadfence();
            g_barGen = gen + 1;
        } else {
            while (g_barGen == gen) { }
        }
    }
    __syncthreads();
}

// ---------------------------------------------------------------------------
// fused counting sort: zero -> hist -> local scan -> block scan -> offsets
// -> scatter, one kernel, 5 grid barriers.
// ---------------------------------------------------------------------------
__global__ void sort_fused_kernel(const int* __restrict__ ei,
                                  const float* __restrict__ ea) {
    __shared__ int s_exc[SORT_CH];
    const int tid = threadIdx.x;
    const int b   = blockIdx.x;
    const int gid = b * SORT_NT + tid;
    const int gstride = SORT_NB * SORT_NT;

    // phase 0: zero histograms
    for (int i = gid; i < Nn; i += gstride) { g_cnt[i] = 0; g_cur[i] = 0; }
    grid_barrier();

    // phase 1: histogram over src
    for (int t = gid; t < Ee; t += gstride)
        atomicAdd(&g_cnt[ei[t]], 1);
    grid_barrier();

    // phase 2: block-local exclusive scan of this block's 68-node chunk
    {
        int idx = b * SORT_CH + tid;
        int v = 0;
        if (tid < SORT_CH && idx < Nn) v = g_cnt[idx];
        if (tid < SORT_CH) s_exc[tid] = v;
        __syncthreads();
        if (tid == 0) {
            int run = 0;
#pragma unroll 4
            for (int i = 0; i < SORT_CH; i++) {
                int c = s_exc[i];
                s_exc[i] = run;
                run += c;
            }
            g_bsum[b] = run;
        }
    }
    grid_barrier();

    // phase 3: block 0 scans the 148 block sums
    if (b == 0 && tid == 0) {
        int run = 0;
#pragma unroll 4
        for (int i = 0; i < SORT_NB; i++) {
            int c = g_bsum[i];
            g_boff[i] = run;
            run += c;
        }
        g_off[Nn] = run;      // == Ee
    }
    grid_barrier();

    // phase 4: write global offsets
    {
        int idx = b * SORT_CH + tid;
        if (tid < SORT_CH && idx < Nn)
            g_off[idx] = g_boff[b] + s_exc[tid];
    }
    grid_barrier();

    // phase 5: scatter edges into src-sorted order
    for (int t = gid; t < Ee; t += gstride) {
        int s = ei[t];
        int p = g_off[s] + atomicAdd(&g_cur[s], 1);
        g_sdst[p] = ei[Ee + t];
        g_sea[p]  = reinterpret_cast<const float2*>(ea)[t];
    }
}

// ---------------------------------------------------------------------------
// layer-0 node init: agg = x·root + bias,  rbuf = x·b2   (din = 4)
// ---------------------------------------------------------------------------
__global__ void aux0_kernel(const float* __restrict__ x,
                            const float* __restrict__ root,
                            const float* __restrict__ bias,
                            const float* __restrict__ b2,
                            float* __restrict__ agg,
                            float* __restrict__ rbuf) {
    int warp = (blockIdx.x * blockDim.x + threadIdx.x) >> 5;
    int lane = threadIdx.x & 31;
    if (warp >= Nn) return;
    float accA = 0.f, accR = 0.f;
#pragma unroll
    for (int i = 0; i < Ff; i++) {
        float xv = x[warp * Ff + i];
        accA = fmaf(xv, root[i * Hh + lane], accA);
        accR = fmaf(xv, b2[i * Hh + lane], accR);
    }
    agg [warp * Hh + lane] = accA + bias[lane];
    rbuf[warp * Hh + lane] = accR;
}

// ---------------------------------------------------------------------------
// layer-0 edge kernel with FOLDED Qn (R11-proven): din=4, qreg built on the
// fly from 4 x-values and w2_0 cached in smem. No g_Qn traffic for layer 0.
// ---------------------------------------------------------------------------
__global__ void edge0_kernel(const float* __restrict__ x,
                             const float* __restrict__ w1,
                             const float* __restrict__ b1,
                             const float* __restrict__ w2,
                             const float* __restrict__ rbuf,
                             float* __restrict__ agg) {
    __shared__ float w2s[Hh * Ff * Hh];        // 16KB
    __shared__ float hs_all[8][32][32];        // 32KB
    const int wip  = threadIdx.x >> 5;
    const int n    = (blockIdx.x * blockDim.x + threadIdx.x) >> 5;
    const int lane = threadIdx.x & 31;

    for (int i = threadIdx.x; i < Hh * Ff * Hh; i += 256)
        w2s[i] = w2[i];
    __syncthreads();

    if (n >= Nn) return;
    const int beg = g_off[n], end = g_off[n + 1];
    if (beg == end) return;
    float (*hs)[32] = hs_all[wip];

    const float w1a = w1[lane], w1b = w1[Hh + lane], b1v = b1[lane];

    float x0 = x[n * Ff + 0], x1 = x[n * Ff + 1];
    float x2 = x[n * Ff + 2], x3 = x[n * Ff + 3];
    float qreg[Hh];
#pragma unroll
    for (int k = 0; k < Hh; k++) {
        const float* w = w2s + k * (Ff * Hh) + lane;
        qreg[k] = fmaf(x0, w[0], fmaf(x1, w[Hh],
                  fmaf(x2, w[2 * Hh], x3 * w[3 * Hh])));
    }
    const float rsrc = rbuf[n * Hh + lane];

    for (int t = beg; t < end; t += 32) {
        const int m = min(32, end - t);
        float2 eav = make_float2(0.f, 0.f);
        int dstv = 0;
        if (lane < m) { eav = g_sea[t + lane]; dstv = g_sdst[t + lane]; }

        for (int e = 0; e < m; e++) {
            float ea0 = __shfl_sync(0xffffffffu, eav.x, e);
            float ea1 = __shfl_sync(0xffffffffu, eav.y, e);
            hs[e][lane] = fmaxf(fmaf(ea0, w1a, fmaf(ea1, w1b, b1v)), 0.f);
        }
        __syncwarp();

        for (int e = 0; e < m; e++) {
            int dst = __shfl_sync(0xffffffffu, dstv, e);
            const float4* hv = reinterpret_cast<const float4*>(hs[e]);
            float a0 = rsrc, a1 = 0.f, a2 = 0.f, a3 = 0.f;
#pragma unroll
            for (int c = 0; c < 8; c++) {
                float4 h4 = hv[c];
                a0 = fmaf(h4.x, qreg[4 * c    ], a0);
                a1 = fmaf(h4.y, qreg[4 * c + 1], a1);
                a2 = fmaf(h4.z, qreg[4 * c + 2], a2);
                a3 = fmaf(h4.w, qreg[4 * c + 3], a3);
            }
            atomicAdd(&agg[dst * Hh + lane], (a0 + a1) + (a2 + a3));
        }
        __syncwarp();
    }
}

// ---------------------------------------------------------------------------
// fused Qn + aux (f32x2 FMA GEMM), layers 1-2 (din = 32)
// ---------------------------------------------------------------------------
template <int DIN>
__global__ void qnaux_kernel(const float* __restrict__ x,
                             const float* __restrict__ w2,
                             const float* __restrict__ root,
                             const float* __restrict__ bias,
                             const float* __restrict__ b2,
                             float* __restrict__ Qn,
                             float* __restrict__ agg,
                             float* __restrict__ rbuf) {
    __shared__ float2 xs2[8][DIN];
    const int nbase = blockIdx.x * 8;
    const int tid = threadIdx.x;

    for (int idx = tid; idx < 8 * DIN; idx += 128) {
        int t = idx / DIN, i = idx % DIN;
        float v = fmaxf(x[(nbase + t) * DIN + i], 0.f);   // relu on load
        xs2[t][i] = make_float2(v, v);
    }
    __syncthreads();

    const int c0 = tid * 8;
    const int k  = c0 >> 5;
    const int ob = c0 & 31;
    const float* wbase = w2 + k * (DIN * Hh) + ob;

    unsigned long long acc[8][4];
#pragma unroll
    for (int t = 0; t < 8; t++)
#pragma unroll
        for (int p = 0; p < 4; p++) acc[t][p] = 0ULL;

#pragma unroll
    for (int i = 0; i < DIN; i++) {
        ulonglong2 wa = *reinterpret_cast<const ulonglong2*>(wbase + i * Hh);
        ulonglong2 wb = *reinterpret_cast<const ulonglong2*>(wbase + i * Hh + 4);
#pragma unroll
        for (int t = 0; t < 8; t++) {
            unsigned long long xv =
                *reinterpret_cast<const unsigned long long*>(&xs2[t][i]);
            asm("fma.rn.f32x2 %0,%1,%2,%0;" : "+l"(acc[t][0]) : "l"(xv), "l"(wa.x));
            asm("fma.rn.f32x2 %0,%1,%2,%0;" : "+l"(acc[t][1]) : "l"(xv), "l"(wa.y));
            asm("fma.rn.f32x2 %0,%1,%2,%0;" : "+l"(acc[t][2]) : "l"(xv), "l"(wb.x));
            asm("fma.rn.f32x2 %0,%1,%2,%0;" : "+l"(acc[t][3]) : "l"(xv), "l"(wb.y));
        }
    }

#pragma unroll
    for (int t = 0; t < 8; t++) {
        float* dst = Qn + (nbase + t) * (Hh * Hh) + c0;
#pragma unroll
        for (int p = 0; p < 4; p++)
            *reinterpret_cast<unsigned long long*>(dst + p * 2) = acc[t][p];
    }

    for (int it = tid; it < 256; it += 128) {
        int t = it >> 5, o = it & 31;
        float accA = 0.f, accR = 0.f;
#pragma unroll
        for (int i = 0; i < DIN; i++) {
            float xv = xs2[t][i].x;
            accA = fmaf(xv, root[i * Hh + o], accA);
            accR = fmaf(xv, b2  [i * Hh + o], accR);
        }
        agg [(nbase + t) * Hh + o] = accA + bias[o];
        rbuf[(nbase + t) * Hh + o] = accR;
    }
}

// ---------------------------------------------------------------------------
// edge stage (layers 1-2), R11-proven: one warp per node, 32-edge tiles,
// scalar atomicAdd scatter.
// ---------------------------------------------------------------------------
__global__ void edge3_kernel(const float* __restrict__ w1,
                             const float* __restrict__ b1,
                             const float* __restrict__ Qn,
                             const float* __restrict__ rbuf,
                             float* __restrict__ agg) {
    __shared__ float hs_all[8][32][32];        // 32KB
    const int wip  = threadIdx.x >> 5;
    const int n    = (blockIdx.x * blockDim.x + threadIdx.x) >> 5;
    const int lane = threadIdx.x & 31;
    if (n >= Nn) return;
    const int beg = g_off[n], end = g_off[n + 1];
    if (beg == end) return;
    float (*hs)[32] = hs_all[wip];

    const float w1a = w1[lane], w1b = w1[Hh + lane], b1v = b1[lane];

    float qreg[Hh];
    const float* __restrict__ q = Qn + n * (Hh * Hh) + lane;
#pragma unroll
    for (int k = 0; k < Hh; k++) qreg[k] = q[k * Hh];
    const float rsrc = rbuf[n * Hh + lane];

    for (int t = beg; t < end; t += 32) {
        const int m = min(32, end - t);
        float2 eav = make_float2(0.f, 0.f);
        int dstv = 0;
        if (lane < m) { eav = g_sea[t + lane]; dstv = g_sdst[t + lane]; }

        for (int e = 0; e < m; e++) {
            float ea0 = __shfl_sync(0xffffffffu, eav.x, e);
            float ea1 = __shfl_sync(0xffffffffu, eav.y, e);
            hs[e][lane] = fmaxf(fmaf(ea0, w1a, fmaf(ea1, w1b, b1v)), 0.f);
        }
        __syncwarp();

        for (int e = 0; e < m; e++) {
            int dst = __shfl_sync(0xffffffffu, dstv, e);
            const float4* hv = reinterpret_cast<const float4*>(hs[e]);
            float a0 = rsrc, a1 = 0.f, a2 = 0.f, a3 = 0.f;
#pragma unroll
            for (int c = 0; c < 8; c++) {
                float4 h4 = hv[c];
                a0 = fmaf(h4.x, qreg[4 * c    ], a0);
                a1 = fmaf(h4.y, qreg[4 * c + 1], a1);
                a2 = fmaf(h4.z, qreg[4 * c + 2], a2);
                a3 = fmaf(h4.w, qreg[4 * c + 3], a3);
            }
            atomicAdd(&agg[dst * Hh + lane], (a0 + a1) + (a2 + a3));
        }
        __syncwarp();
    }
}

// ---------------------------------------------------------------------------
__global__ void fc_kernel(const float* __restrict__ xr,
                          const float* __restrict__ fcw,
                          const float* __restrict__ fcb,
                          float* __restrict__ out) {
    int warp = (blockIdx.x * blockDim.x + threadIdx.x) >> 5;
    int lane = threadIdx.x & 31;
    if (warp >= Nn) return;

    float xv = fmaxf(xr[warp * Hh + lane], 0.f);
    float lg[Cc];
#pragma unroll
    for (int c = 0; c < Cc; c++) {
        float p = xv * fcw[lane * Cc + c];
#pragma unroll
        for (int s = 16; s > 0; s >>= 1)
            p += __shfl_xor_sync(0xffffffffu, p, s);
        lg[c] = p + fcb[c];
    }
    float m = fmaxf(fmaxf(lg[0], lg[1]), fmaxf(lg[2], lg[3]));
    float se = 0.f;
#pragma unroll
    for (int c = 0; c < Cc; c++) se += __expf(lg[c] - m);
    float lse = m + __logf(se);
    if (lane < Cc) out[warp * Cc + lane] = lg[lane] - lse;
}

// ---------------------------------------------------------------------------
extern "C" void kernel_launch(void* const* d_in, const int* in_sizes, int n_in,
                              void* d_out, int out_size) {
    (void)in_sizes; (void)n_in; (void)out_size;

    const float* x  = (const float*)d_in[0];
    const int*   ei = (const int*)  d_in[1];
    const float* ea = (const float*)d_in[2];
    const float* w1[3];  const float* b1[3];  const float* w2[3];
    const float* b2[3];  const float* rt[3];  const float* bs[3];
    for (int l = 0; l < 3; l++) {
        w1[l] = (const float*)d_in[3 + 6 * l + 0];
        b1[l] = (const float*)d_in[3 + 6 * l + 1];
        w2[l] = (const float*)d_in[3 + 6 * l + 2];
        b2[l] = (const float*)d_in[3 + 6 * l + 3];
        rt[l] = (const float*)d_in[3 + 6 * l + 4];
        bs[l] = (const float*)d_in[3 + 6 * l + 5];
    }
    const float* fcw = (const float*)d_in[21];
    const float* fcb = (const float*)d_in[22];
    float* out = (float*)d_out;

    float *Qn, *rbuf, *xA, *xB;
    cudaGetSymbolAddress((void**)&Qn,   g_Qn);
    cudaGetSymbolAddress((void**)&rbuf, g_r);
    cudaGetSymbolAddress((void**)&xA,   g_xA);
    cudaGetSymbolAddress((void**)&xB,   g_xB);

    const int qnBlocks       = Nn / 8;                 // 1250
    const int nodeWarpBlocks = (Nn * 32 + 255) / 256;  // 1250

    // (1) layer-0 node init (independent of sort)
    aux0_kernel<<<nodeWarpBlocks, 256>>>(x, rt[0], bs[0], b2[0], xA, rbuf);

    // (2) fused counting sort: zero+hist+scan+scatter in one kernel
    sort_fused_kernel<<<SORT_NB, SORT_NT>>>(ei, ea);

    // (3) layer 0 edges (folded Qn)
    edge0_kernel<<<nodeWarpBlocks, 256>>>(x, w1[0], b1[0], w2[0], rbuf, xA);

    // (4) layer 1 Qn+aux  <-- ncu capture slot (4th launch)
    qnaux_kernel<Hh><<<qnBlocks, 128>>>(xA, w2[1], rt[1], bs[1], b2[1], Qn, xB, rbuf);

    // (5) layer 1 edges
    edge3_kernel<<<nodeWarpBlocks, 256>>>(w1[1], b1[1], Qn, rbuf, xB);

    // (6) layer 2 Qn+aux
    qnaux_kernel<Hh><<<qnBlocks, 128>>>(xB, w2[2], rt[2], bs[2], b2[2], Qn, xA, rbuf);

    // (7) layer 2 edges
    edge3_kernel<<<nodeWarpBlocks, 256>>>(w1[2], b1[2], Qn, rbuf, xA);

    // (8) FC + log_softmax
    fc_kernel<<<nodeWarpBlocks, 256>>>(xA, fcw, fcb, out);
}